// round 17
// baseline (speedup 1.0000x reference)
#include <cuda_runtime.h>
#include <cuda_bf16.h>
#include <cuda_fp16.h>
#include <math.h>
#include <stdint.h>

// ---------------------------------------------------------------------------
// Encoder layer: B=1, S=4096, D=1024, H=16, dk=64, F=4096, fp32 in/out.
// R17 = R16 GEMMs/LN/packs + attention at 3 CTAs/SM (64-key tiles, reg cap
// 170) for 12 warps/SM on the latency-exposed flash kernel.
// ---------------------------------------------------------------------------

#define S_LEN 4096
#define D_MODEL 1024
#define D_FF 4096
#define NUM_HEADS 16
#define DK 64
#define QKV_N 3072

__device__ __nv_bfloat16 g_h1b[S_LEN * D_MODEL];
__device__ __nv_bfloat16 g_Qb[S_LEN * D_MODEL];
__device__ __nv_bfloat16 g_Kb[S_LEN * D_MODEL];
__device__ __nv_bfloat16 g_Vb[S_LEN * D_MODEL];
__device__ __nv_bfloat16 g_Vt[D_MODEL * S_LEN];    // [dim][key]
__device__ uint32_t g_ctxh[S_LEN * (D_MODEL / 2)]; // ctx fp16 pairs
__device__ float g_x1[S_LEN * D_MODEL];
__device__ uint32_t g_h2h[S_LEN * (D_MODEL / 2)];  // LN2 out fp16 pairs
__device__ uint32_t g_f1h[S_LEN * (D_FF / 2)];     // FFN1 out fp16 pairs
__device__ uint32_t g_W3b[(D_MODEL / 2) * QKV_N];  // bf16 k-pair packed
__device__ float g_b3[QKV_N];
__device__ uint32_t g_WoP[(D_MODEL / 2) * D_MODEL];
__device__ uint32_t g_W1P[(D_MODEL / 2) * D_FF];
__device__ uint32_t g_W2P[(D_FF / 2) * D_MODEL];

// ---------------------------------------------------------------------------
__device__ __forceinline__ void mma_bf16(float (&d)[4],
    const uint32_t (&a)[4], uint32_t b0, uint32_t b1)
{
    asm volatile(
        "mma.sync.aligned.m16n8k16.row.col.f32.bf16.bf16.f32 "
        "{%0,%1,%2,%3}, {%4,%5,%6,%7}, {%8,%9}, {%0,%1,%2,%3};\n"
        : "+f"(d[0]), "+f"(d[1]), "+f"(d[2]), "+f"(d[3])
        : "r"(a[0]), "r"(a[1]), "r"(a[2]), "r"(a[3]), "r"(b0), "r"(b1));
}
__device__ __forceinline__ void mma_f16(float (&d)[4],
    const uint32_t (&a)[4], uint32_t b0, uint32_t b1)
{
    asm volatile(
        "mma.sync.aligned.m16n8k16.row.col.f32.f16.f16.f32 "
        "{%0,%1,%2,%3}, {%4,%5,%6,%7}, {%8,%9}, {%0,%1,%2,%3};\n"
        : "+f"(d[0]), "+f"(d[1]), "+f"(d[2]), "+f"(d[3])
        : "r"(a[0]), "r"(a[1]), "r"(a[2]), "r"(a[3]), "r"(b0), "r"(b1));
}
__device__ __forceinline__ void ldsm_x4(uint32_t (&d)[4], uint32_t saddr) {
    asm volatile("ldmatrix.sync.aligned.m8n8.x4.shared.b16 {%0,%1,%2,%3}, [%4];"
        : "=r"(d[0]), "=r"(d[1]), "=r"(d[2]), "=r"(d[3]) : "r"(saddr));
}
__device__ __forceinline__ void ldsm_x2(uint32_t& d0, uint32_t& d1, uint32_t saddr) {
    asm volatile("ldmatrix.sync.aligned.m8n8.x2.shared.b16 {%0,%1}, [%2];"
        : "=r"(d0), "=r"(d1) : "r"(saddr));
}
__device__ __forceinline__ uint32_t smem_u32(const void* p) {
    return (uint32_t)__cvta_generic_to_shared(p);
}
__device__ __forceinline__ uint32_t pack_bf16(float lo, float hi) {
    __nv_bfloat162 v = __floats2bfloat162_rn(lo, hi);
    return *(uint32_t*)&v;
}
__device__ __forceinline__ uint32_t pack_f16(float lo, float hi) {
    __half2 v = __floats2half2_rn(lo, hi);
    return *(uint32_t*)&v;
}
#define CP_ASYNC16(dst, src) \
    asm volatile("cp.async.cg.shared.global [%0], [%1], 16;\n" :: "r"(dst), "l"(src))
#define CP_COMMIT() asm volatile("cp.async.commit_group;\n")
#define CP_WAIT(n)  asm volatile("cp.async.wait_group %0;\n" :: "n"(n))

__device__ __forceinline__ float ex2(float x) {
    float y;
    asm("ex2.approx.f32 %0, %1;" : "=f"(y) : "f"(x));
    return y;
}

// ---------------------------------------------------------------------------
// Concat + pack Wq|Wk|Wv -> W3b (bf16 k-pairs, vectorized x4), b3
// ---------------------------------------------------------------------------
__global__ __launch_bounds__(256) void concat3b(
    const float* __restrict__ Wq, const float* __restrict__ Wk,
    const float* __restrict__ Wv, const float* __restrict__ bq,
    const float* __restrict__ bk, const float* __restrict__ bv,
    uint32_t* __restrict__ W3b, float* __restrict__ b3)
{
    const int t = blockIdx.x * 256 + threadIdx.x;
    const int idx = t * 4;
    const int kp = idx / QKV_N, n = idx % QKV_N;
    const int sel = n >> 10, col = n & 1023;
    const float* W = sel == 0 ? Wq : (sel == 1 ? Wk : Wv);
    float4 lo = *(const float4*)&W[(size_t)(2 * kp) * D_MODEL + col];
    float4 hi = *(const float4*)&W[(size_t)(2 * kp + 1) * D_MODEL + col];
    uint4 o;
    o.x = pack_bf16(lo.x, hi.x);
    o.y = pack_bf16(lo.y, hi.y);
    o.z = pack_bf16(lo.z, hi.z);
    o.w = pack_bf16(lo.w, hi.w);
    *(uint4*)&W3b[(size_t)kp * QKV_N + n] = o;
    if (idx < QKV_N) {
#pragma unroll
        for (int j = 0; j < 4; j++) {
            const int nn = n + j, ss = nn >> 10, cc = nn & 1023;
            const float* b = ss == 0 ? bq : (ss == 1 ? bk : bv);
            b3[nn] = b[cc];
        }
    }
}

// Fused pack: Wo (1024x1024), W1 (1024x4096), W2 (4096x1024) -> fp16 k-pairs
#define PACK_Q0 (D_MODEL / 2 * D_MODEL / 4)
#define PACK_Q1 (D_MODEL / 2 * D_FF / 4)
#define PACK_Q2 (D_FF / 2 * D_MODEL / 4)
__global__ __launch_bounds__(256) void pack_all(
    const float* __restrict__ Wo, const float* __restrict__ W1,
    const float* __restrict__ W2, uint32_t* __restrict__ WoP,
    uint32_t* __restrict__ W1P, uint32_t* __restrict__ W2P)
{
    int t = blockIdx.x * 256 + threadIdx.x;
    const float* W;
    uint32_t* Wp;
    int N;
    if (t < PACK_Q0) {
        W = Wo; Wp = WoP; N = D_MODEL;
    } else if (t < PACK_Q0 + PACK_Q1) {
        t -= PACK_Q0; W = W1; Wp = W1P; N = D_FF;
    } else {
        t -= PACK_Q0 + PACK_Q1; W = W2; Wp = W2P; N = D_MODEL;
    }
    const size_t idx = (size_t)t * 4;
    const int kp = (int)(idx / N), n = (int)(idx % N);
    float4 lo = *(const float4*)&W[(size_t)(2 * kp) * N + n];
    float4 hi = *(const float4*)&W[(size_t)(2 * kp + 1) * N + n];
    uint4 o;
    o.x = pack_f16(lo.x, hi.x);
    o.y = pack_f16(lo.y, hi.y);
    o.z = pack_f16(lo.z, hi.z);
    o.w = pack_f16(lo.w, hi.w);
    *(uint4*)&Wp[idx] = o;
}

// ---------------------------------------------------------------------------
// V [S,1024] bf16 -> Vt [1024,S] bf16 (transpose)
// ---------------------------------------------------------------------------
__global__ __launch_bounds__(256) void vtrans_b(
    const __nv_bfloat16* __restrict__ V, __nv_bfloat16* __restrict__ Vt)
{
    __shared__ float t[64][33];
    const int k0 = blockIdx.x * 64;
    const int d0 = blockIdx.y * 32;
    const int x = threadIdx.x & 31;
    const int y = threadIdx.x >> 5;
#pragma unroll
    for (int i = 0; i < 64; i += 8)
        t[y + i][x] = __bfloat162float(V[(size_t)(k0 + y + i) * D_MODEL + d0 + x]);
    __syncthreads();
    uint32_t* Vt32 = (uint32_t*)Vt;
#pragma unroll
    for (int p = 0; p < 4; p++) {
        const int d = y + 8 * p;
        const int j = x;
        uint32_t v = pack_bf16(t[2 * j][d], t[2 * j + 1][d]);
        Vt32[(size_t)(d0 + d) * (S_LEN / 2) + (k0 >> 1) + j] = v;
    }
}

// ---------------------------------------------------------------------------
// LayerNorm. OUT: 0=fp32, 1=bf16 pairs, 2=fp16 pairs.
// ---------------------------------------------------------------------------
template<int OUT>
__global__ __launch_bounds__(256) void ln_kernel(
    const float* __restrict__ x, const float* __restrict__ alpha,
    const float* __restrict__ beta, void* __restrict__ yv)
{
    const int row = blockIdx.x;
    const float4* xr = (const float4*)(x + (size_t)row * D_MODEL);
    const int tid = threadIdx.x;

    float4 xl = xr[tid];
    float s = xl.x + xl.y + xl.z + xl.w;

    __shared__ float sh[8];
#pragma unroll
    for (int o = 16; o > 0; o >>= 1) s += __shfl_xor_sync(0xffffffffu, s, o);
    if ((tid & 31) == 0) sh[tid >> 5] = s;
    __syncthreads();
    float mu = 0.f;
#pragma unroll
    for (int i = 0; i < 8; i++) mu += sh[i];
    mu *= (1.0f / D_MODEL);
    __syncthreads();

    float dx = xl.x - mu, dy = xl.y - mu, dz = xl.z - mu, dw = xl.w - mu;
    float v = dx * dx + dy * dy + dz * dz + dw * dw;
#pragma unroll
    for (int o = 16; o > 0; o >>= 1) v += __shfl_xor_sync(0xffffffffu, v, o);
    if ((tid & 31) == 0) sh[tid >> 5] = v;
    __syncthreads();
    float var = 0.f;
#pragma unroll
    for (int i = 0; i < 8; i++) var += sh[i];
    var *= (1.0f / (D_MODEL - 1));

    const float a = alpha[0], b = beta[0];
    const float inv = a / (sqrtf(var) + 1e-6f);
    float ox = dx * inv + b, oy = dy * inv + b;
    float oz = dz * inv + b, ow = dw * inv + b;
    if (OUT == 1) {
        uint32_t* yr = (uint32_t*)yv + (size_t)row * (D_MODEL / 2);
        yr[2 * tid + 0] = pack_bf16(ox, oy);
        yr[2 * tid + 1] = pack_bf16(oz, ow);
    } else if (OUT == 2) {
        uint32_t* yr = (uint32_t*)yv + (size_t)row * (D_MODEL / 2);
        yr[2 * tid + 0] = pack_f16(ox, oy);
        yr[2 * tid + 1] = pack_f16(oz, ow);
    } else {
        float4* yr = (float4*)yv + (size_t)row * (D_MODEL / 4);
        yr[tid] = make_float4(ox, oy, oz, ow);
    }
}

// ---------------------------------------------------------------------------
// 16-bit GEMM core: BM=128 BN=128 BK=64 (32 u32 kpair rows), 256 threads,
// 8 warps (64x32 tiles), 3-stage cp.async, 1 barrier per 64-K tile, 2 CTAs/SM.
// ---------------------------------------------------------------------------
#define QASTR 36
#define QBSTR 136
#define QA_TILE (128 * QASTR)
#define QB_TILE (32 * QBSTR)
#define QSTG_U  (QA_TILE + QB_TILE)
#define G16_SMEM (3 * QSTG_U * 4)

// ---- bf16 QKV GEMM ----
__global__ __launch_bounds__(256, 2) void mm_qkv_bf16(
    const uint32_t* __restrict__ A, const uint32_t* __restrict__ W3b,
    const float* __restrict__ bias,
    __nv_bfloat16* __restrict__ Q, __nv_bfloat16* __restrict__ Kout,
    __nv_bfloat16* __restrict__ V)
{
    extern __shared__ uint32_t smq[];

    const int tid  = threadIdx.x;
    const int warp = tid >> 5, lane = tid & 31;
    const int r = lane >> 2, c = lane & 3;
    const int wm = (warp >> 2) * 64, wn = (warp & 3) * 32;
    const int m0 = blockIdx.y * 128, n0 = blockIdx.x * 128;
    const int KU = D_MODEL / 2;

    const uint32_t s0 = smem_u32(smq);
    const int g2 = lane >> 3, rowin = lane & 7;
    const uint32_t aLane = (uint32_t)(((g2 & 1) * 8 + rowin) * QASTR + (g2 >> 1) * 4) * 4u;

    float acc[4][4][4];
#pragma unroll
    for (int i = 0; i < 4; i++)
#pragma unroll
        for (int j = 0; j < 4; j++)
#pragma unroll
            for (int k = 0; k < 4; k++) acc[i][j][k] = 0.f;

    const int NK = KU >> 5;

    auto load_tile = [&](int kt, int st) {
        const uint32_t ab = s0 + (uint32_t)(st * QSTG_U) * 4u;
        const uint32_t bb = ab + (uint32_t)QA_TILE * 4u;
#pragma unroll
        for (int i = 0; i < 4; i++) {
            const int id = tid + 256 * i;
            const int ar = id >> 3, akc = id & 7;
            CP_ASYNC16(ab + (uint32_t)(ar * QASTR + akc * 4) * 4u,
                       A + (size_t)(m0 + ar) * KU + kt * 32 + akc * 4);
            const int br = id >> 5, bnc = id & 31;
            CP_ASYNC16(bb + (uint32_t)(br * QBSTR + bnc * 4) * 4u,
                       W3b + (size_t)(kt * 32 + br) * QKV_N + n0 + bnc * 4);
        }
    };

    load_tile(0, 0);
    CP_COMMIT();
    load_tile(1, 1);
    CP_COMMIT();

    for (int kt = 0; kt < NK; kt++) {
        const int st = kt - (kt / 3) * 3;
        CP_WAIT(1);
        __syncthreads();
        if (kt + 2 < NK) {
            const int s2 = (kt + 2) - ((kt + 2) / 3) * 3;
            load_tile(kt + 2, s2);
        }
        CP_COMMIT();

        const uint32_t aWarp = s0 + (uint32_t)(st * QSTG_U + wm * QASTR) * 4u + aLane;
        const uint32_t* Bb = smq + st * QSTG_U + QA_TILE;
#pragma unroll
        for (int ks = 0; ks < 4; ks++) {
            uint32_t a[4][4], b[4][2];
#pragma unroll
            for (int fm = 0; fm < 4; fm++)
                ldsm_x4(a[fm], aWarp + (uint32_t)((fm * 16 * QASTR + ks * 8) * 4));
#pragma unroll
            for (int fn = 0; fn < 4; fn++) {
                const uint32_t* q = Bb + (ks * 8 + c) * QBSTR + wn + fn * 8 + r;
                b[fn][0] = q[0];
                b[fn][1] = q[4 * QBSTR];
            }
#pragma unroll
            for (int fm = 0; fm < 4; fm++)
#pragma unroll
                for (int fn = 0; fn < 4; fn++)
                    mma_bf16(acc[fm][fn], a[fm], b[fn][0], b[fn][1]);
        }
    }

    const int sel = n0 >> 10;
    const int nl0 = n0 & 1023;
    __nv_bfloat16* Cb = sel == 0 ? Q : (sel == 1 ? Kout : V);
#pragma unroll
    for (int fm = 0; fm < 4; fm++) {
        const int row0 = m0 + wm + fm * 16 + r;
        const int row1 = row0 + 8;
#pragma unroll
        for (int fn = 0; fn < 4; fn++) {
            const int colg = n0 + wn + fn * 8 + 2 * c;
            const int col  = nl0 + wn + fn * 8 + 2 * c;
            float2 bi = *(const float2*)&bias[colg];
            *(uint32_t*)&Cb[(size_t)row0 * 1024 + col] =
                pack_bf16(acc[fm][fn][0] + bi.x, acc[fm][fn][1] + bi.y);
            *(uint32_t*)&Cb[(size_t)row1 * 1024 + col] =
                pack_bf16(acc[fm][fn][2] + bi.x, acc[fm][fn][3] + bi.y);
        }
    }
}

// ---- fp16 generic GEMM ----
template<bool RELU, bool RES, bool OUT16>
__global__ __launch_bounds__(256, 2) void mm_f16k(
    const uint32_t* __restrict__ A, const uint32_t* __restrict__ Wp,
    const float* __restrict__ bias, const float* __restrict__ Rsd,
    float* __restrict__ Cf, uint32_t* __restrict__ Ch,
    int M, int N, int KU)
{
    extern __shared__ uint32_t smq[];

    const int tid  = threadIdx.x;
    const int warp = tid >> 5, lane = tid & 31;
    const int r = lane >> 2, c = lane & 3;
    const int wm = (warp >> 2) * 64, wn = (warp & 3) * 32;
    const int m0 = blockIdx.y * 128, n0 = blockIdx.x * 128;

    const uint32_t s0 = smem_u32(smq);
    const int g2 = lane >> 3, rowin = lane & 7;
    const uint32_t aLane = (uint32_t)(((g2 & 1) * 8 + rowin) * QASTR + (g2 >> 1) * 4) * 4u;

    float acc[4][4][4];
#pragma unroll
    for (int i = 0; i < 4; i++)
#pragma unroll
        for (int j = 0; j < 4; j++)
#pragma unroll
            for (int k = 0; k < 4; k++) acc[i][j][k] = 0.f;

    const int NK = KU >> 5;

    auto load_tile = [&](int kt, int st) {
        const uint32_t ab = s0 + (uint32_t)(st * QSTG_U) * 4u;
        const uint32_t bb = ab + (uint32_t)QA_TILE * 4u;
#pragma unroll
        for (int i = 0; i < 4; i++) {
            const int id = tid + 256 * i;
            const int ar = id >> 3, akc = id & 7;
            CP_ASYNC16(ab + (uint32_t)(ar * QASTR + akc * 4) * 4u,
                       A + (size_t)(m0 + ar) * KU + kt * 32 + akc * 4);
            const int br = id >> 5, bnc = id & 31;
            CP_ASYNC16(bb + (uint32_t)(br * QBSTR + bnc * 4) * 4u,
                       Wp + (size_t)(kt * 32 + br) * N + n0 + bnc * 4);
        }
    };

    load_tile(0, 0);
    CP_COMMIT();
    load_tile(1, 1);
    CP_COMMIT();

    for (int kt = 0; kt < NK; kt++) {
        const int st = kt - (kt / 3) * 3;
        CP_WAIT(1);
        __syncthreads();
        if (kt + 2 < NK) {
            const int s2 = (kt + 2) - ((kt + 2) / 3) * 3;
            load_tile(kt + 2, s2);
        }
        CP_COMMIT();

        const uint32_t aWarp = s0 + (uint32_t)(st * QSTG_U + wm * QASTR) * 4u + aLane;
        const uint32_t* Bb = smq + st * QSTG_U + QA_TILE;
#pragma unroll
        for (int ks = 0; ks < 4; ks++) {
            uint32_t a[4][4], b[4][2];
#pragma unroll
            for (int fm = 0; fm < 4; fm++)
                ldsm_x4(a[fm], aWarp + (uint32_t)((fm * 16 * QASTR + ks * 8) * 4));
#pragma unroll
            for (int fn = 0; fn < 4; fn++) {
                const uint32_t* q = Bb + (ks * 8 + c) * QBSTR + wn + fn * 8 + r;
                b[fn][0] = q[0];
                b[fn][1] = q[4 * QBSTR];
            }
#pragma unroll
            for (int fm = 0; fm < 4; fm++)
#pragma unroll
                for (int fn = 0; fn < 4; fn++)
                    mma_f16(acc[fm][fn], a[fm], b[fn][0], b[fn][1]);
        }
    }

#pragma unroll
    for (int fm = 0; fm < 4; fm++) {
        const int row0 = m0 + wm + fm * 16 + r;
        const int row1 = row0 + 8;
#pragma unroll
        for (int fn = 0; fn < 4; fn++) {
            const int col = n0 + wn + fn * 8 + 2 * c;
            float2 bi = *(const float2*)&bias[col];
            float v0 = acc[fm][fn][0] + bi.x;
            float v1 = acc[fm][fn][1] + bi.y;
            float v2 = acc[fm][fn][2] + bi.x;
            float v3 = acc[fm][fn][3] + bi.y;
            if (RELU) {
                v0 = fmaxf(v0, 0.f); v1 = fmaxf(v1, 0.f);
                v2 = fmaxf(v2, 0.f); v3 = fmaxf(v3, 0.f);
            }
            if (RES) {
                float2 r0 = *(const float2*)&Rsd[(size_t)row0 * N + col];
                float2 r1 = *(const float2*)&Rsd[(size_t)row1 * N + col];
                v0 += r0.x; v1 += r0.y; v2 += r1.x; v3 += r1.y;
            }
            if (OUT16) {
                const int cu = (col >> 1);
                Ch[(size_t)row0 * (N >> 1) + cu] = pack_f16(v0, v1);
                Ch[(size_t)row1 * (N >> 1) + cu] = pack_f16(v2, v3);
            } else {
                *(float2*)&Cf[(size_t)row0 * N + col] = make_float2(v0, v1);
                *(float2*)&Cf[(size_t)row1 * N + col] = make_float2(v2, v3);
            }
        }
    }
}

// ---------------------------------------------------------------------------
// Flash attention, bf16 m16n8k16. grid = (S/128, H), 128 threads, 3 CTAs/SM
// (64-key double-buffered tiles, reg cap 170 -> 12 warps/SM).
// ---------------------------------------------------------------------------
#define ASTRU 36
#define QTILE_U (128 * ASTRU)
#define KTILE_U (64 * ASTRU)
#define ATT_SMEM ((QTILE_U + 4 * KTILE_U) * 4)     // 55296 B
#define QK_SCALE 0.1803368801111364f               // 0.125 * log2(e)

__global__ __launch_bounds__(128, 3) void attn_bf16(
    const __nv_bfloat16* __restrict__ Qm, const __nv_bfloat16* __restrict__ Km,
    const __nv_bfloat16* __restrict__ Vt, uint32_t* __restrict__ CtxH)
{
    extern __shared__ uint32_t su[];
    uint32_t* Qs = su;
    uint32_t* Ks = Qs + QTILE_U;
    uint32_t* Vs = Ks + 2 * KTILE_U;

    const int tid  = threadIdx.x;
    const int warp = tid >> 5, lane = tid & 31;
    const int r = lane >> 2, c = lane & 3;
    const int wr = warp * 32;
    const int qb = blockIdx.x, h = blockIdx.y;
    const int cb = h * DK;

    const uint32_t qdst = smem_u32(Qs);
    const uint32_t kdst = smem_u32(Ks);
    const uint32_t vdst = smem_u32(Vs);

    const int g2 = lane >> 3, rowin = lane & 7;
    const uint32_t qLane = (uint32_t)(((g2 & 1) * 8 + rowin) * ASTRU + (g2 >> 1) * 4) * 4u;
    const uint32_t kLane = (uint32_t)(rowin * ASTRU + (g2 & 1) * 4) * 4u;

#pragma unroll
    for (int i = 0; i < 8; i++) {
        int id = tid + 128 * i;
        int row = id >> 3, ch = id & 7;
        CP_ASYNC16(qdst + (uint32_t)(row * ASTRU + ch * 4) * 4u,
                   Qm + (size_t)(qb * 128 + row) * D_MODEL + cb + ch * 8);
    }
#pragma unroll
    for (int i = 0; i < 4; i++) {
        int id = tid + 128 * i;
        int row = id >> 3, ch = id & 7;
        CP_ASYNC16(kdst + (uint32_t)(row * ASTRU + ch * 4) * 4u,
                   Km + (size_t)row * D_MODEL + cb + ch * 8);
        CP_ASYNC16(vdst + (uint32_t)(row * ASTRU + ch * 4) * 4u,
                   Vt + (size_t)(cb + row) * S_LEN + ch * 8);
    }
    CP_COMMIT();
    CP_WAIT(0);
    __syncthreads();

    const uint32_t qWarp = qdst + (uint32_t)(wr * ASTRU) * 4u + qLane;

    float mrow[2][2] = {{-1e30f, -1e30f}, {-1e30f, -1e30f}};
    float lrow[2][2] = {{0.f, 0.f}, {0.f, 0.f}};
    float acc[2][8][4];
#pragma unroll
    for (int i = 0; i < 2; i++)
#pragma unroll
        for (int j = 0; j < 8; j++)
#pragma unroll
            for (int k = 0; k < 4; k++) acc[i][j][k] = 0.f;

    for (int kt = 0; kt < S_LEN / 64; kt++) {
        const int buf = kt & 1;

        if (kt > 0) {
            CP_WAIT(0);
            __syncthreads();
        }
        if (kt + 1 < S_LEN / 64) {
            const int nb = buf ^ 1;
#pragma unroll
            for (int i = 0; i < 4; i++) {
                int id = tid + 128 * i;
                int row = id >> 3, ch = id & 7;
                CP_ASYNC16(kdst + (uint32_t)(nb * KTILE_U + row * ASTRU + ch * 4) * 4u,
                           Km + (size_t)((kt + 1) * 64 + row) * D_MODEL + cb + ch * 8);
                CP_ASYNC16(vdst + (uint32_t)(nb * KTILE_U + row * ASTRU + ch * 4) * 4u,
                           Vt + (size_t)(cb + row) * S_LEN + (kt + 1) * 64 + ch * 8);
            }
            CP_COMMIT();
        }

        float s[2][8][4];
#pragma unroll
        for (int i = 0; i < 2; i++)
#pragma unroll
            for (int j = 0; j < 8; j++)
#pragma unroll
                for (int k = 0; k < 4; k++) s[i][j][k] = 0.f;

        const uint32_t kTile = kdst + (uint32_t)(buf * KTILE_U) * 4u + kLane;
#pragma unroll
        for (int ks = 0; ks < 4; ks++) {
            uint32_t qf0[4], qf1[4];
            ldsm_x4(qf0, qWarp + (uint32_t)((ks * 8) * 4));
            ldsm_x4(qf1, qWarp + (uint32_t)((16 * ASTRU + ks * 8) * 4));
#pragma unroll
            for (int fn = 0; fn < 8; fn++) {
                uint32_t b0, b1;
                ldsm_x2(b0, b1, kTile + (uint32_t)((8 * fn * ASTRU + ks * 8) * 4));
                mma_bf16(s[0][fn], qf0, b0, b1);
                mma_bf16(s[1][fn], qf1, b0, b1);
            }
        }

        uint32_t pa[2][4][4];
#pragma unroll
        for (int fm = 0; fm < 2; fm++) {
            float mx0 = -1e30f, mx1 = -1e30f;
#pragma unroll
            for (int fn = 0; fn < 8; fn++) {
                mx0 = fmaxf(mx0, fmaxf(s[fm][fn][0], s[fm][fn][1]));
                mx1 = fmaxf(mx1, fmaxf(s[fm][fn][2], s[fm][fn][3]));
            }
            mx0 = fmaxf(mx0, __shfl_xor_sync(0xffffffffu, mx0, 1));
            mx0 = fmaxf(mx0, __shfl_xor_sync(0xffffffffu, mx0, 2));
            mx1 = fmaxf(mx1, __shfl_xor_sync(0xffffffffu, mx1, 1));
            mx1 = fmaxf(mx1, __shfl_xor_sync(0xffffffffu, mx1, 2));

            const float mn0 = fmaxf(mrow[fm][0], mx0);
            const float mn1 = fmaxf(mrow[fm][1], mx1);
            const float emn0 = mn0 * QK_SCALE;
            const float emn1 = mn1 * QK_SCALE;
            const float sc0 = ex2(fmaf(mrow[fm][0], QK_SCALE, -emn0));
            const float sc1 = ex2(fmaf(mrow[fm][1], QK_SCALE, -emn1));
            float ls0 = 0.f, ls1 = 0.f;
#pragma unroll
            for (int fn = 0; fn < 8; fn++) {
                float e0 = ex2(fmaf(s[fm][fn][0], QK_SCALE, -emn0));
                float e1 = ex2(fmaf(s[fm][fn][1], QK_SCALE, -emn0));
                float e2 = ex2(fmaf(s[fm][fn][2], QK_SCALE, -emn1));
                float e3 = ex2(fmaf(s[fm][fn][3], QK_SCALE, -emn1));
                ls0 += e0 + e1;
                ls1 += e2 + e3;
                pa[fm][fn >> 1][(fn & 1) * 2 + 0] = pack_bf16(e0, e1);
                pa[fm][fn >> 1][(fn & 1) * 2 + 1] = pack_bf16(e2, e3);
            }
            ls0 += __shfl_xor_sync(0xffffffffu, ls0, 1);
            ls0 += __shfl_xor_sync(0xffffffffu, ls0, 2);
            ls1 += __shfl_xor_sync(0xffffffffu, ls1, 1);
            ls1 += __shfl_xor_sync(0xffffffffu, ls1, 2);

            lrow[fm][0] = lrow[fm][0] * sc0 + ls0;
            lrow[fm][1] = lrow[fm][1] * sc1 + ls1;
            mrow[fm][0] = mn0; mrow[fm][1] = mn1;

#pragma unroll
            for (int fn = 0; fn < 8; fn++) {
                acc[fm][fn][0] *= sc0; acc[fm][fn][1] *= sc0;
                acc[fm][fn][2] *= sc1; acc[fm][fn][3] *= sc1;
            }
        }

        const uint32_t vTile = vdst + (uint32_t)(buf * KTILE_U) * 4u + kLane;
#pragma unroll
        for (int ks = 0; ks < 4; ks++) {
#pragma unroll
            for (int fn = 0; fn < 8; fn++) {
                uint32_t b0, b1;
                ldsm_x2(b0, b1, vTile + (uint32_t)((8 * fn * ASTRU + ks * 8) * 4));
                mma_bf16(acc[0][fn], pa[0][ks], b0, b1);
                mma_bf16(acc[1][fn], pa[1][ks], b0, b1);
            }
        }
    }

#pragma unroll
    for (int fm = 0; fm < 2; fm++) {
        const float inv0 = 1.f / lrow[fm][0];
        const float inv1 = 1.f / lrow[fm][1];
        const int row0 = qb * 128 + wr + fm * 16 + r;
        const int row1 = row0 + 8;
#pragma unroll
        for (int fn = 0; fn < 8; fn++) {
            const int cu = ((cb + fn * 8) >> 1) + c;
            CtxH[(size_t)row0 * (D_MODEL / 2) + cu] =
                pack_f16(acc[fm][fn][0] * inv0, acc[fm][fn][1] * inv0);
            CtxH[(size_t)row1 * (D_MODEL / 2) + cu] =
                pack_f16(acc[fm][fn][2] * inv1, acc[fm][fn][3] * inv1);
        }
    }
}

// ---------------------------------------------------------------------------
extern "C" void kernel_launch(void* const* d_in, const int* in_sizes, int n_in,
                              void* d_out, int out_size)
{
    const float* x    = (const float*)d_in[0];
    const float* Wq   = (const float*)d_in[1];
    const float* bq   = (const float*)d_in[2];
    const float* Wk   = (const float*)d_in[3];
    const float* bk   = (const float*)d_in[4];
    const float* Wv   = (const float*)d_in[5];
    const float* bv   = (const float*)d_in[6];
    const float* Wo   = (const float*)d_in[7];
    const float* bo   = (const float*)d_in[8];
    const float* ln1a = (const float*)d_in[9];
    const float* ln1b = (const float*)d_in[10];
    const float* W1   = (const float*)d_in[11];
    const float* b1   = (const float*)d_in[12];
    const float* W2   = (const float*)d_in[13];
    const float* b2   = (const float*)d_in[14];
    const float* ln2a = (const float*)d_in[15];
    const float* ln2b = (const float*)d_in[16];
    float* out = (float*)d_out;

    float *x1, *b3;
    __nv_bfloat16 *h1b, *Qb, *Kb, *Vb, *Vt;
    uint32_t *W3b, *ctxh, *h2h, *f1h, *WoP, *W1P, *W2P;
    cudaGetSymbolAddress((void**)&h1b,  g_h1b);
    cudaGetSymbolAddress((void**)&Qb,   g_Qb);
    cudaGetSymbolAddress((void**)&Kb,   g_Kb);
    cudaGetSymbolAddress((void**)&Vb,   g_Vb);
    cudaGetSymbolAddress((void**)&Vt,   g_Vt);
    cudaGetSymbolAddress((void**)&ctxh, g_ctxh);
    cudaGetSymbolAddress((void**)&x1,   g_x1);
    cudaGetSymbolAddress((void**)&h2h,  g_h2h);
    cudaGetSymbolAddress((void**)&f1h,  g_f1h);
    cudaGetSymbolAddress((void**)&W3b,  g_W3b);
    cudaGetSymbolAddress((void**)&b3,   g_b3);
    cudaGetSymbolAddress((void**)&WoP,  g_WoP);
    cudaGetSymbolAddress((void**)&W1P,  g_W1P);
    cudaGetSymbolAddress((void**)&W2P,  g_W2P);

    cudaFuncSetAttribute(mm_qkv_bf16,
                         cudaFuncAttributeMaxDynamicSharedMemorySize, G16_SMEM);
    cudaFuncSetAttribute(mm_f16k<false, true, false>,
                         cudaFuncAttributeMaxDynamicSharedMemorySize, G16_SMEM);
    cudaFuncSetAttribute(mm_f16k<true, false, true>,
                         cudaFuncAttributeMaxDynamicSharedMemorySize, G16_SMEM);
    cudaFuncSetAttribute(attn_bf16,
                         cudaFuncAttributeMaxDynamicSharedMemorySize, ATT_SMEM);

    // one-time packs
    concat3b<<<(D_MODEL / 2) * QKV_N / 1024, 256>>>(Wq, Wk, Wv, bq, bk, bv, W3b, b3);
    pack_all<<<(PACK_Q0 + PACK_Q1 + PACK_Q2) / 256, 256>>>(Wo, W1, W2, WoP, W1P, W2P);

    const dim3 gQKV (QKV_N  / 128, S_LEN / 128);     // (24, 32)
    const dim3 gSmall(D_MODEL / 128, S_LEN / 128);   // (8, 32)
    const dim3 gFF1 (D_FF   / 128, S_LEN / 128);     // (32, 32)

    // residual 1
    ln_kernel<1><<<S_LEN, 256>>>(x, ln1a, ln1b, h1b);
    mm_qkv_bf16<<<gQKV, 256, G16_SMEM>>>((const uint32_t*)h1b, W3b, b3, Qb, Kb, Vb);
    vtrans_b<<<dim3(S_LEN / 64, D_MODEL / 32), 256>>>(Vb, Vt);
    attn_bf16<<<dim3(S_LEN / 128, NUM_HEADS), 128, ATT_SMEM>>>(Qb, Kb, Vt, ctxh);
    mm_f16k<false, true, false><<<gSmall, 256, G16_SMEM>>>(
        ctxh, WoP, bo, x, x1, nullptr, S_LEN, D_MODEL, D_MODEL / 2);

    // residual 2
    ln_kernel<2><<<S_LEN, 256>>>(x1, ln2a, ln2b, h2h);
    mm_f16k<true, false, true><<<gFF1, 256, G16_SMEM>>>(
        h2h, W1P, b1, nullptr, nullptr, f1h, S_LEN, D_FF, D_MODEL / 2);
    mm_f16k<false, true, false><<<gSmall, 256, G16_SMEM>>>(
        f1h, W2P, b2, x1, out, nullptr, S_LEN, D_MODEL, D_FF / 2);
}